// round 15
// baseline (speedup 1.0000x reference)
#include <cuda_runtime.h>
#include <cuda_fp16.h>
#include <cstdint>

#define DIN  128
#define DOUT 128
#define EDIM 16
#define MAXN 50176
#define MAXE 819200
#define BN_EPS 1e-5f

// ---------------- device scratch (static; zero-initialized at load) ---------
// Invariant: g_cnt, g_sum, g_sumsq, g_ea are ZERO at the start of every run
// (statics zero-init; each run re-zeroes after use).
__device__ __half g_x [MAXN * DOUT];   // feats @ W_rel^T + b_rel  (fp16)
__device__ float g_res[MAXN * DOUT];   // relu(feats @ W_res^T + b_res)
__device__ float g_h  [MAXN * DOUT];   // pre-BN activations
__device__ float g_ea [MAXN * EDIM];   // scatter-add of edge_attr per dst
__device__ int   g_cnt[MAXN];          // per-dst degree (histogram)
__device__ int   g_off[MAXN + 1];      // CSR offsets
__device__ int   g_cur[MAXN];          // placement cursors
__device__ int   g_csr_src[MAXE];      // src node per CSR slot
__device__ float g_sum  [DOUT];
__device__ float g_sumsq[DOUT];
__device__ float g_scale[DOUT];
__device__ float g_shift[DOUT];
__device__ int   g_is64;               // edge_index dtype flag

__device__ __forceinline__ void red_add_v4(float* p, float4 v) {
    asm volatile("red.global.add.v4.f32 [%0], {%1,%2,%3,%4};"
                 :: "l"(p), "f"(v.x), "f"(v.y), "f"(v.z), "f"(v.w)
                 : "memory");
}

__device__ __forceinline__ uint32_t cvt_tf32(float a) {
    uint32_t r;
    asm("cvt.rna.tf32.f32 %0, %1;" : "=r"(r) : "f"(a));
    return r;
}

__device__ __forceinline__ void mma_tf32(float* d, const uint32_t* a, const uint32_t* b) {
    asm volatile(
        "mma.sync.aligned.m16n8k8.row.col.f32.tf32.tf32.f32 "
        "{%0,%1,%2,%3}, {%4,%5,%6,%7}, {%8,%9}, {%0,%1,%2,%3};"
        : "+f"(d[0]), "+f"(d[1]), "+f"(d[2]), "+f"(d[3])
        : "r"(a[0]), "r"(a[1]), "r"(a[2]), "r"(a[3]), "r"(b[0]), "r"(b[1]));
}

// ---------------- K_hist: per-block dtype detect + histogram over dst --------
__global__ __launch_bounds__(256)
void k_hist(const void* __restrict__ ei_raw, int E)
{
    __shared__ int blk_nz;
    const unsigned int* w = (const unsigned int*)ei_raw;
    if (threadIdx.x == 0) blk_nz = 0;
    __syncthreads();
    if (w[2 * threadIdx.x + 1] != 0u) atomicOr(&blk_nz, 1);
    __syncthreads();
    const int is64 = blk_nz ? 0 : 1;
    if (blockIdx.x == 0 && threadIdx.x == 0) g_is64 = is64;

    int e = blockIdx.x * blockDim.x + threadIdx.x;
    if (e >= E) return;
    int d = is64 ? (int)((const long long*)ei_raw)[E + e]
                 : ((const int*)ei_raw)[E + e];
    atomicAdd(&g_cnt[d], 1);
}

// ---------------- K_scanall: single-block coalesced exclusive scan -----------
// 1024 threads; round r loads g_cnt[r*1024 + tid] (coalesced), block-scans,
// adds running carry. Consumes g_cnt (writes 0 back).
__global__ __launch_bounds__(1024)
void k_scanall(int N)
{
    __shared__ int wsum[32];
    __shared__ int s_carry;
    const int tid = threadIdx.x, wid = tid >> 5, lane = tid & 31;
    if (tid == 0) s_carry = 0;
    __syncthreads();

    const int rounds = (N + 1023) / 1024;
    for (int r = 0; r < rounds; r++) {
        int i = r * 1024 + tid;
        int v = (i < N) ? g_cnt[i] : 0;
        int x = v;
        #pragma unroll
        for (int o = 1; o < 32; o <<= 1) {
            int y = __shfl_up_sync(0xffffffffu, x, o);
            if (lane >= o) x += y;
        }
        if (lane == 31) wsum[wid] = x;
        __syncthreads();
        if (wid == 0) {                      // full warp, 32 warp-sums
            int s = wsum[lane];
            #pragma unroll
            for (int o = 1; o < 32; o <<= 1) {
                int y = __shfl_up_sync(0xffffffffu, s, o);
                if (lane >= o) s += y;
            }
            wsum[lane] = s;                  // inclusive scan of warp sums
        }
        __syncthreads();
        int woff = (wid > 0) ? wsum[wid - 1] : 0;
        int excl = s_carry + woff + x - v;
        if (i < N) {
            g_off[i] = excl;
            g_cur[i] = excl;
            g_cnt[i] = 0;                    // restore zero-invariant
        }
        __syncthreads();                     // all reads of s_carry done
        if (tid == 0) s_carry += wsum[31];
        __syncthreads();                     // carry visible for next round
    }
    if (tid == 0) g_off[N] = s_carry;
}

// ---------------- K1 body (device): tf32 GEMM tile ---------------------------
#define K1_KT       64
#define K1_PITCH    68
#define K1_AS_FL    (128 * K1_PITCH)        // 8704 floats
#define K1_BF_FL    (8 * 8 * 32 * 4)        // 8192 floats
#define K1_SMEM     ((K1_AS_FL + K1_BF_FL) * 4)   // 67584 bytes

__device__ void k1_body(int bx, int yy,
                        const float* __restrict__ feats,
                        const float* __restrict__ Wrel, const float* __restrict__ brel,
                        const float* __restrict__ Wres, const float* __restrict__ bres,
                        int N, float* smem)
{
    float* As = smem;              // [128][68] fp32
    float* Bf = smem + K1_AS_FL;   // frag-major B hi/lo

    const int tid   = threadIdx.x;
    const int m0    = bx * 128;
    const int mat   = yy >> 1;
    const int nhalf = yy & 1;

    const float* Wsel = (mat == 0) ? Wrel : Wres;
    const float* bsel = (mat == 0) ? brel : bres;
    const int nbase = nhalf * 64;

    const int warp = tid >> 5, lane = tid & 31;
    const int g = lane >> 2, tig = lane & 3;
    const int mwarp = warp >> 1;
    const int nwarp = warp & 1;
    const int am0 = mwarp * 32;

    float d[2][4][4];
    #pragma unroll
    for (int mi = 0; mi < 2; mi++)
        #pragma unroll
        for (int ns = 0; ns < 4; ns++)
            #pragma unroll
            for (int q = 0; q < 4; q++) d[mi][ns][q] = 0.f;

    for (int kt = 0; kt < DIN / K1_KT; kt++) {
        const int koff = kt * K1_KT;
        __syncthreads();
        for (int idx = tid; idx < 128 * 16; idx += 256) {
            int row = idx >> 4, c4 = idx & 15;
            int node = m0 + row;
            float4 v = (node < N)
                ? *(const float4*)&feats[(size_t)node * DIN + koff + c4 * 4]
                : make_float4(0.f, 0.f, 0.f, 0.f);
            *(float4*)&As[row * K1_PITCH + c4 * 4] = v;
        }
        for (int idx = tid; idx < 8 * 8 * 32; idx += 256) {
            int ks = idx >> 8;
            int ns = (idx >> 5) & 7;
            int ln = idx & 31;
            int gg = ln >> 2, tg = ln & 3;
            int nrow = nbase + ns * 8 + gg;
            const float* wr = &Wsel[(size_t)nrow * DIN + koff + ks * 8 + tg];
            float w0 = wr[0], w1 = wr[4];
            uint32_t h0 = cvt_tf32(w0);
            uint32_t h1 = cvt_tf32(w1);
            uint32_t l0 = cvt_tf32(w0 - __uint_as_float(h0));
            uint32_t l1 = cvt_tf32(w1 - __uint_as_float(h1));
            *(float4*)&Bf[(size_t)idx * 4] =
                make_float4(__uint_as_float(h0), __uint_as_float(h1),
                            __uint_as_float(l0), __uint_as_float(l1));
        }
        __syncthreads();

        #pragma unroll
        for (int ks = 0; ks < K1_KT / 8; ks++) {
            const int k0 = ks * 8;
            float af[8];
            #pragma unroll
            for (int mi = 0; mi < 2; mi++) {
                int r0 = am0 + mi * 16 + g;
                af[mi*4+0] = As[r0 * K1_PITCH + k0 + tig];
                af[mi*4+1] = As[(r0 + 8) * K1_PITCH + k0 + tig];
                af[mi*4+2] = As[r0 * K1_PITCH + k0 + tig + 4];
                af[mi*4+3] = As[(r0 + 8) * K1_PITCH + k0 + tig + 4];
            }
            uint32_t ah[8], al[8];
            #pragma unroll
            for (int q = 0; q < 8; q++) {
                ah[q] = cvt_tf32(af[q]);
                al[q] = cvt_tf32(af[q] - __uint_as_float(ah[q]));
            }
            #pragma unroll
            for (int nsl = 0; nsl < 4; nsl++) {
                const int nsg = nwarp * 4 + nsl;
                float4 b = *(const float4*)&Bf[((ks * 8 + nsg) * 32 + lane) * 4];
                uint32_t bh[2] = {__float_as_uint(b.x), __float_as_uint(b.y)};
                uint32_t bl[2] = {__float_as_uint(b.z), __float_as_uint(b.w)};
                #pragma unroll
                for (int mi = 0; mi < 2; mi++) {
                    mma_tf32(d[mi][nsl], ah + 4*mi, bh);
                    mma_tf32(d[mi][nsl], al + 4*mi, bh);
                    mma_tf32(d[mi][nsl], ah + 4*mi, bl);
                }
            }
        }
    }

    #pragma unroll
    for (int mi = 0; mi < 2; mi++) {
        const int rA = m0 + am0 + mi * 16 + g;
        #pragma unroll
        for (int nsl = 0; nsl < 4; nsl++) {
            const int col = nbase + (nwarp * 4 + nsl) * 8 + tig * 2;
            float b0 = bsel[col], b1 = bsel[col + 1];
            float v0 = d[mi][nsl][0] + b0, v1 = d[mi][nsl][1] + b1;
            float v2 = d[mi][nsl][2] + b0, v3 = d[mi][nsl][3] + b1;
            if (mat == 0) {
                if (rA < N)
                    *(__half2*)&g_x[(size_t)rA * DOUT + col] = __floats2half2_rn(v0, v1);
                if (rA + 8 < N)
                    *(__half2*)&g_x[(size_t)(rA + 8) * DOUT + col] = __floats2half2_rn(v2, v3);
            } else {
                v0 = fmaxf(v0, 0.f); v1 = fmaxf(v1, 0.f);
                v2 = fmaxf(v2, 0.f); v3 = fmaxf(v3, 0.f);
                if (rA < N)
                    *(float2*)&g_res[(size_t)rA * DOUT + col] = make_float2(v0, v1);
                if (rA + 8 < N)
                    *(float2*)&g_res[(size_t)(rA + 8) * DOUT + col] = make_float2(v2, v3);
            }
        }
    }
}

// ---------------- place body (device) ----------------------------------------
__device__ void place_body(int blk, const void* __restrict__ ei_raw,
                           const float* __restrict__ eattr, int E)
{
    int e = blk * 256 + threadIdx.x;
    if (e >= E) return;
    int s, d;
    if (g_is64) {
        const long long* p = (const long long*)ei_raw;
        s = (int)p[e]; d = (int)p[E + e];
    } else {
        const int* p = (const int*)ei_raw;
        s = p[e]; d = p[E + e];
    }
    int pos = atomicAdd(&g_cur[d], 1);
    g_csr_src[pos] = s;

    const float4* a4 = (const float4*)&eattr[(size_t)e * EDIM];
    float* dst = &g_ea[(size_t)d * EDIM];
    red_add_v4(dst + 0,  a4[0]);
    red_add_v4(dst + 4,  a4[1]);
    red_add_v4(dst + 8,  a4[2]);
    red_add_v4(dst + 12, a4[3]);
}

// ---------------- K_fused: k1 GEMM blocks + place blocks in one launch -------
// bid < k1_blocks -> GEMM tile (long blocks first); else -> place block.
// Independent work co-resident on SMs: tensor-bound and memory-bound overlap.
__global__ __launch_bounds__(256)
void k_fused(const void* __restrict__ ei_raw, const float* __restrict__ eattr, int E,
             const float* __restrict__ feats,
             const float* __restrict__ Wrel, const float* __restrict__ brel,
             const float* __restrict__ Wres, const float* __restrict__ bres,
             int N, int k1_blocks)
{
    extern __shared__ float smem[];
    int bid = blockIdx.x;
    if (bid < k1_blocks) {
        k1_body(bid >> 2, bid & 3, feats, Wrel, brel, Wres, bres, N, smem);
    } else {
        place_body(bid - k1_blocks, ei_raw, eattr, E);
    }
}

// ---------------- K_pull: fp16 gather + combine + BN partials ----------------
__global__ __launch_bounds__(256)
void k_pull(const float* __restrict__ We, const float* __restrict__ be, int N)
{
    __shared__ float s_sum[128];
    __shared__ float s_sq[128];
    int tid = threadIdx.x;
    if (tid < 128) { s_sum[tid] = 0.f; s_sq[tid] = 0.f; }
    __syncthreads();

    int warp = tid >> 5, lane = tid & 31;
    int n = blockIdx.x * 8 + warp;

    if (n < N) {
        const int j0 = g_off[n], j1 = g_off[n + 1];
        const int c0 = lane * 4;

        float4 acc = make_float4(0.f, 0.f, 0.f, 0.f);

        for (int base = j0; base < j1; base += 32) {
            int myidx = g_csr_src[base + lane];   // coalesced; overread bounded by MAXE
            int cnt = j1 - base; if (cnt > 32) cnt = 32;
            int t = 0;
            for (; t + 3 < cnt; t += 4) {
                int s0 = __shfl_sync(0xffffffffu, myidx, t);
                int s1 = __shfl_sync(0xffffffffu, myidx, t + 1);
                int s2 = __shfl_sync(0xffffffffu, myidx, t + 2);
                int s3 = __shfl_sync(0xffffffffu, myidx, t + 3);
                uint2 r0 = *(const uint2*)&g_x[(size_t)s0 * DOUT + c0];
                uint2 r1 = *(const uint2*)&g_x[(size_t)s1 * DOUT + c0];
                uint2 r2 = *(const uint2*)&g_x[(size_t)s2 * DOUT + c0];
                uint2 r3 = *(const uint2*)&g_x[(size_t)s3 * DOUT + c0];
                float2 a0 = __half22float2(*(__half2*)&r0.x);
                float2 b0 = __half22float2(*(__half2*)&r0.y);
                float2 a1 = __half22float2(*(__half2*)&r1.x);
                float2 b1 = __half22float2(*(__half2*)&r1.y);
                float2 a2 = __half22float2(*(__half2*)&r2.x);
                float2 b2 = __half22float2(*(__half2*)&r2.y);
                float2 a3 = __half22float2(*(__half2*)&r3.x);
                float2 b3 = __half22float2(*(__half2*)&r3.y);
                acc.x += (a0.x + a1.x) + (a2.x + a3.x);
                acc.y += (a0.y + a1.y) + (a2.y + a3.y);
                acc.z += (b0.x + b1.x) + (b2.x + b3.x);
                acc.w += (b0.y + b1.y) + (b2.y + b3.y);
            }
            for (; t < cnt; t++) {
                int s0 = __shfl_sync(0xffffffffu, myidx, t);
                uint2 r0 = *(const uint2*)&g_x[(size_t)s0 * DOUT + c0];
                float2 a0 = __half22float2(*(__half2*)&r0.x);
                float2 b0 = __half22float2(*(__half2*)&r0.y);
                acc.x += a0.x; acc.y += a0.y; acc.z += b0.x; acc.w += b0.y;
            }
        }

        float ea = 0.f;
        if (lane < EDIM) {
            ea = g_ea[(size_t)n * EDIM + lane];
            g_ea[(size_t)n * EDIM + lane] = 0.f;   // restore zero-invariant
        }
        float eav[EDIM];
        #pragma unroll
        for (int q = 0; q < EDIM; q++) eav[q] = __shfl_sync(0xffffffffu, ea, q);

        const float deg = (float)(j1 - j0);
        float4 b = *(const float4*)&be[c0];
        float4 elin = make_float4(b.x * deg, b.y * deg, b.z * deg, b.w * deg);

        const float4* W4 = (const float4*)We;
        #pragma unroll
        for (int q4 = 0; q4 < 4; q4++) {
            float4 w0 = W4[(c0 + 0) * 4 + q4];
            float4 w1 = W4[(c0 + 1) * 4 + q4];
            float4 w2 = W4[(c0 + 2) * 4 + q4];
            float4 w3 = W4[(c0 + 3) * 4 + q4];
            float e0v = eav[q4 * 4 + 0], e1v = eav[q4 * 4 + 1];
            float e2v = eav[q4 * 4 + 2], e3v = eav[q4 * 4 + 3];
            elin.x += w0.x * e0v + w0.y * e1v + w0.z * e2v + w0.w * e3v;
            elin.y += w1.x * e0v + w1.y * e1v + w1.z * e2v + w1.w * e3v;
            elin.z += w2.x * e0v + w2.y * e1v + w2.z * e2v + w2.w * e3v;
            elin.w += w3.x * e0v + w3.y * e1v + w3.z * e2v + w3.w * e3v;
        }

        float4 res = *(const float4*)&g_res[(size_t)n * DOUT + c0];
        float4 h;
        h.x = fmaxf(acc.x + elin.x, 0.f) + res.x;
        h.y = fmaxf(acc.y + elin.y, 0.f) + res.y;
        h.z = fmaxf(acc.z + elin.z, 0.f) + res.z;
        h.w = fmaxf(acc.w + elin.w, 0.f) + res.w;
        *(float4*)&g_h[(size_t)n * DOUT + c0] = h;

        atomicAdd(&s_sum[c0 + 0], h.x);
        atomicAdd(&s_sum[c0 + 1], h.y);
        atomicAdd(&s_sum[c0 + 2], h.z);
        atomicAdd(&s_sum[c0 + 3], h.w);
        atomicAdd(&s_sq[c0 + 0], h.x * h.x);
        atomicAdd(&s_sq[c0 + 1], h.y * h.y);
        atomicAdd(&s_sq[c0 + 2], h.z * h.z);
        atomicAdd(&s_sq[c0 + 3], h.w * h.w);
    }

    __syncthreads();
    if (tid < 128) {
        atomicAdd(&g_sum[tid],   s_sum[tid]);
        atomicAdd(&g_sumsq[tid], s_sq[tid]);
    }
}

// ---------------- K4: finalize BN stats (consumes + resets accumulators) -----
__global__ void k4_stats(const float* __restrict__ gamma,
                         const float* __restrict__ beta, int N)
{
    int c = threadIdx.x;
    float invN = 1.f / (float)N;
    float s  = g_sum[c];
    float s2 = g_sumsq[c];
    g_sum[c] = 0.f;
    g_sumsq[c] = 0.f;
    float mean = s * invN;
    float var  = s2 * invN - mean * mean;
    float rstd = rsqrtf(var + BN_EPS);
    float sc   = gamma[c] * rstd;
    g_scale[c] = sc;
    g_shift[c] = beta[c] - mean * sc;
}

// ---------------- K5: normalize ----------------------------------------------
__global__ __launch_bounds__(256)
void k5_norm(float* __restrict__ out, int total4)
{
    int idx = blockIdx.x * blockDim.x + threadIdx.x;
    if (idx >= total4) return;
    int c4 = (idx & (DOUT / 4 - 1)) * 4;
    float4 h  = *(const float4*)&g_h[idx * 4];
    float4 sc = *(const float4*)&g_scale[c4];
    float4 sh = *(const float4*)&g_shift[c4];
    float4 o;
    o.x = h.x * sc.x + sh.x;
    o.y = h.y * sc.y + sh.y;
    o.z = h.z * sc.z + sh.z;
    o.w = h.w * sc.w + sh.w;
    ((float4*)out)[idx] = o;
}

// ---------------- launch ------------------------------------------------------
extern "C" void kernel_launch(void* const* d_in, const int* in_sizes, int n_in,
                              void* d_out, int out_size)
{
    const float* feats = (const float*)d_in[0];
    const void*  ei    = d_in[1];
    const float* eattr = (const float*)d_in[2];
    const float* Wrel  = (const float*)d_in[3];
    const float* brel  = (const float*)d_in[4];
    const float* We    = (const float*)d_in[5];
    const float* be    = (const float*)d_in[6];
    const float* Wres  = (const float*)d_in[7];
    const float* bres  = (const float*)d_in[8];
    const float* gamma = (const float*)d_in[9];
    const float* beta  = (const float*)d_in[10];

    const int N = in_sizes[0] / DIN;
    const int E = in_sizes[2] / EDIM;

    static int smem_set = 0;
    if (!smem_set) {
        cudaFuncSetAttribute(k_fused,
                             cudaFuncAttributeMaxDynamicSharedMemorySize, K1_SMEM);
        smem_set = 1;
    }

    const int k1_blocks = ((N + 127) / 128) * 4;
    const int pl_blocks = (E + 255) / 256;

    // order: k_pull is launch #4 (the ncu-profiled launch)
    k_hist<<<(E + 255) / 256, 256>>>(ei, E);
    k_scanall<<<1, 1024>>>(N);
    k_fused<<<k1_blocks + pl_blocks, 256, K1_SMEM>>>(
        ei, eattr, E, feats, Wrel, brel, Wres, bres, N, k1_blocks);
    k_pull<<<(N + 7) / 8, 256>>>(We, be, N);
    k4_stats<<<1, 128>>>(gamma, beta, N);
    int total4 = N * DOUT / 4;
    k5_norm<<<(total4 + 255) / 256, 256>>>((float*)d_out, total4);
}

// round 16
// speedup vs baseline: 1.1049x; 1.1049x over previous
#include <cuda_runtime.h>
#include <cuda_fp16.h>
#include <cstdint>

#define DIN  128
#define DOUT 128
#define EDIM 16
#define MAXN 50176
#define MAXE 819200
#define BN_EPS 1e-5f

// ---------------- device scratch (static; zero-initialized at load) ---------
// Invariant: g_cnt, g_sum, g_sumsq, g_ea are ZERO at the start of every run
// (statics zero-init; each run re-zeroes after use).
__device__ __half g_x [MAXN * DOUT];   // feats @ W_rel^T + b_rel  (fp16)
__device__ float g_res[MAXN * DOUT];   // relu(feats @ W_res^T + b_res)
__device__ float g_h  [MAXN * DOUT];   // pre-BN activations
__device__ float g_ea [MAXN * EDIM];   // scatter-add of edge_attr per dst
__device__ int   g_cnt[MAXN];          // per-dst degree (histogram)
__device__ int   g_off[MAXN + 1];      // CSR offsets
__device__ int   g_cur[MAXN];          // placement cursors
__device__ int   g_csr_src[MAXE];      // src node per CSR slot
__device__ float g_sum  [DOUT];
__device__ float g_sumsq[DOUT];
__device__ float g_scale[DOUT];
__device__ float g_shift[DOUT];
__device__ int   g_is64;               // edge_index dtype flag

__device__ __forceinline__ void red_add_v4(float* p, float4 v) {
    asm volatile("red.global.add.v4.f32 [%0], {%1,%2,%3,%4};"
                 :: "l"(p), "f"(v.x), "f"(v.y), "f"(v.z), "f"(v.w)
                 : "memory");
}

__device__ __forceinline__ uint32_t cvt_tf32(float a) {
    uint32_t r;
    asm("cvt.rna.tf32.f32 %0, %1;" : "=r"(r) : "f"(a));
    return r;
}

__device__ __forceinline__ void mma_tf32(float* d, const uint32_t* a, const uint32_t* b) {
    asm volatile(
        "mma.sync.aligned.m16n8k8.row.col.f32.tf32.tf32.f32 "
        "{%0,%1,%2,%3}, {%4,%5,%6,%7}, {%8,%9}, {%0,%1,%2,%3};"
        : "+f"(d[0]), "+f"(d[1]), "+f"(d[2]), "+f"(d[3])
        : "r"(a[0]), "r"(a[1]), "r"(a[2]), "r"(a[3]), "r"(b[0]), "r"(b[1]));
}

// ---------------- K_hist: per-block dtype detect + histogram over dst --------
__global__ __launch_bounds__(256)
void k_hist(const void* __restrict__ ei_raw, int E)
{
    __shared__ int blk_nz;
    const unsigned int* w = (const unsigned int*)ei_raw;
    if (threadIdx.x == 0) blk_nz = 0;
    __syncthreads();
    if (w[2 * threadIdx.x + 1] != 0u) atomicOr(&blk_nz, 1);
    __syncthreads();
    const int is64 = blk_nz ? 0 : 1;
    if (blockIdx.x == 0 && threadIdx.x == 0) g_is64 = is64;

    int e = blockIdx.x * blockDim.x + threadIdx.x;
    if (e >= E) return;
    int d = is64 ? (int)((const long long*)ei_raw)[E + e]
                 : ((const int*)ei_raw)[E + e];
    atomicAdd(&g_cnt[d], 1);
}

// ---------------- K_scanall: single-block coalesced exclusive scan -----------
__global__ __launch_bounds__(1024)
void k_scanall(int N)
{
    __shared__ int wsum[32];
    __shared__ int s_carry;
    const int tid = threadIdx.x, wid = tid >> 5, lane = tid & 31;
    if (tid == 0) s_carry = 0;
    __syncthreads();

    const int rounds = (N + 1023) / 1024;
    for (int r = 0; r < rounds; r++) {
        int i = r * 1024 + tid;
        int v = (i < N) ? g_cnt[i] : 0;
        int x = v;
        #pragma unroll
        for (int o = 1; o < 32; o <<= 1) {
            int y = __shfl_up_sync(0xffffffffu, x, o);
            if (lane >= o) x += y;
        }
        if (lane == 31) wsum[wid] = x;
        __syncthreads();
        if (wid == 0) {
            int s = wsum[lane];
            #pragma unroll
            for (int o = 1; o < 32; o <<= 1) {
                int y = __shfl_up_sync(0xffffffffu, s, o);
                if (lane >= o) s += y;
            }
            wsum[lane] = s;
        }
        __syncthreads();
        int woff = (wid > 0) ? wsum[wid - 1] : 0;
        int excl = s_carry + woff + x - v;
        if (i < N) {
            g_off[i] = excl;
            g_cur[i] = excl;
            g_cnt[i] = 0;                    // restore zero-invariant
        }
        __syncthreads();
        if (tid == 0) s_carry += wsum[31];
        __syncthreads();
    }
    if (tid == 0) g_off[N] = s_carry;
}

// ---------------- K1 body (device): tf32 GEMM tile ---------------------------
#define K1_KT       64
#define K1_PITCH    68
#define K1_AS_FL    (128 * K1_PITCH)        // 8704 floats
#define K1_BF_FL    (8 * 8 * 32 * 4)        // 8192 floats
#define K1_SMEM     ((K1_AS_FL + K1_BF_FL) * 4)   // 67584 bytes

__device__ void k1_body(int bx, int yy,
                        const float* __restrict__ feats,
                        const float* __restrict__ Wrel, const float* __restrict__ brel,
                        const float* __restrict__ Wres, const float* __restrict__ bres,
                        int N, float* smem)
{
    float* As = smem;
    float* Bf = smem + K1_AS_FL;

    const int tid   = threadIdx.x;
    const int m0    = bx * 128;
    const int mat   = yy >> 1;
    const int nhalf = yy & 1;

    const float* Wsel = (mat == 0) ? Wrel : Wres;
    const float* bsel = (mat == 0) ? brel : bres;
    const int nbase = nhalf * 64;

    const int warp = tid >> 5, lane = tid & 31;
    const int g = lane >> 2, tig = lane & 3;
    const int mwarp = warp >> 1;
    const int nwarp = warp & 1;
    const int am0 = mwarp * 32;

    float d[2][4][4];
    #pragma unroll
    for (int mi = 0; mi < 2; mi++)
        #pragma unroll
        for (int ns = 0; ns < 4; ns++)
            #pragma unroll
            for (int q = 0; q < 4; q++) d[mi][ns][q] = 0.f;

    for (int kt = 0; kt < DIN / K1_KT; kt++) {
        const int koff = kt * K1_KT;
        __syncthreads();
        for (int idx = tid; idx < 128 * 16; idx += 256) {
            int row = idx >> 4, c4 = idx & 15;
            int node = m0 + row;
            float4 v = (node < N)
                ? *(const float4*)&feats[(size_t)node * DIN + koff + c4 * 4]
                : make_float4(0.f, 0.f, 0.f, 0.f);
            *(float4*)&As[row * K1_PITCH + c4 * 4] = v;
        }
        for (int idx = tid; idx < 8 * 8 * 32; idx += 256) {
            int ks = idx >> 8;
            int ns = (idx >> 5) & 7;
            int ln = idx & 31;
            int gg = ln >> 2, tg = ln & 3;
            int nrow = nbase + ns * 8 + gg;
            const float* wr = &Wsel[(size_t)nrow * DIN + koff + ks * 8 + tg];
            float w0 = wr[0], w1 = wr[4];
            uint32_t h0 = cvt_tf32(w0);
            uint32_t h1 = cvt_tf32(w1);
            uint32_t l0 = cvt_tf32(w0 - __uint_as_float(h0));
            uint32_t l1 = cvt_tf32(w1 - __uint_as_float(h1));
            *(float4*)&Bf[(size_t)idx * 4] =
                make_float4(__uint_as_float(h0), __uint_as_float(h1),
                            __uint_as_float(l0), __uint_as_float(l1));
        }
        __syncthreads();

        #pragma unroll
        for (int ks = 0; ks < K1_KT / 8; ks++) {
            const int k0 = ks * 8;
            float af[8];
            #pragma unroll
            for (int mi = 0; mi < 2; mi++) {
                int r0 = am0 + mi * 16 + g;
                af[mi*4+0] = As[r0 * K1_PITCH + k0 + tig];
                af[mi*4+1] = As[(r0 + 8) * K1_PITCH + k0 + tig];
                af[mi*4+2] = As[r0 * K1_PITCH + k0 + tig + 4];
                af[mi*4+3] = As[(r0 + 8) * K1_PITCH + k0 + tig + 4];
            }
            uint32_t ah[8], al[8];
            #pragma unroll
            for (int q = 0; q < 8; q++) {
                ah[q] = cvt_tf32(af[q]);
                al[q] = cvt_tf32(af[q] - __uint_as_float(ah[q]));
            }
            #pragma unroll
            for (int nsl = 0; nsl < 4; nsl++) {
                const int nsg = nwarp * 4 + nsl;
                float4 b = *(const float4*)&Bf[((ks * 8 + nsg) * 32 + lane) * 4];
                uint32_t bh[2] = {__float_as_uint(b.x), __float_as_uint(b.y)};
                uint32_t bl[2] = {__float_as_uint(b.z), __float_as_uint(b.w)};
                #pragma unroll
                for (int mi = 0; mi < 2; mi++) {
                    mma_tf32(d[mi][nsl], ah + 4*mi, bh);
                    mma_tf32(d[mi][nsl], al + 4*mi, bh);
                    mma_tf32(d[mi][nsl], ah + 4*mi, bl);
                }
            }
        }
    }

    #pragma unroll
    for (int mi = 0; mi < 2; mi++) {
        const int rA = m0 + am0 + mi * 16 + g;
        #pragma unroll
        for (int nsl = 0; nsl < 4; nsl++) {
            const int col = nbase + (nwarp * 4 + nsl) * 8 + tig * 2;
            float b0 = bsel[col], b1 = bsel[col + 1];
            float v0 = d[mi][nsl][0] + b0, v1 = d[mi][nsl][1] + b1;
            float v2 = d[mi][nsl][2] + b0, v3 = d[mi][nsl][3] + b1;
            if (mat == 0) {
                if (rA < N)
                    *(__half2*)&g_x[(size_t)rA * DOUT + col] = __floats2half2_rn(v0, v1);
                if (rA + 8 < N)
                    *(__half2*)&g_x[(size_t)(rA + 8) * DOUT + col] = __floats2half2_rn(v2, v3);
            } else {
                v0 = fmaxf(v0, 0.f); v1 = fmaxf(v1, 0.f);
                v2 = fmaxf(v2, 0.f); v3 = fmaxf(v3, 0.f);
                if (rA < N)
                    *(float2*)&g_res[(size_t)rA * DOUT + col] = make_float2(v0, v1);
                if (rA + 8 < N)
                    *(float2*)&g_res[(size_t)(rA + 8) * DOUT + col] = make_float2(v2, v3);
            }
        }
    }
}

// ---------------- place body (device) ----------------------------------------
__device__ void place_body(int blk, const void* __restrict__ ei_raw,
                           const float* __restrict__ eattr, int E)
{
    int e = blk * 256 + threadIdx.x;
    if (e >= E) return;
    int s, d;
    if (g_is64) {
        const long long* p = (const long long*)ei_raw;
        s = (int)p[e]; d = (int)p[E + e];
    } else {
        const int* p = (const int*)ei_raw;
        s = p[e]; d = p[E + e];
    }
    int pos = atomicAdd(&g_cur[d], 1);
    g_csr_src[pos] = s;

    const float4* a4 = (const float4*)&eattr[(size_t)e * EDIM];
    float* dst = &g_ea[(size_t)d * EDIM];
    red_add_v4(dst + 0,  a4[0]);
    red_add_v4(dst + 4,  a4[1]);
    red_add_v4(dst + 8,  a4[2]);
    red_add_v4(dst + 12, a4[3]);
}

// ---------------- K_fused: k1 GEMM blocks + place blocks in one launch -------
__global__ __launch_bounds__(256)
void k_fused(const void* __restrict__ ei_raw, const float* __restrict__ eattr, int E,
             const float* __restrict__ feats,
             const float* __restrict__ Wrel, const float* __restrict__ brel,
             const float* __restrict__ Wres, const float* __restrict__ bres,
             int N, int k1_blocks)
{
    extern __shared__ float smem[];
    int bid = blockIdx.x;
    if (bid < k1_blocks) {
        k1_body(bid >> 2, bid & 3, feats, Wrel, brel, Wres, bres, N, smem);
    } else {
        place_body(bid - k1_blocks, ei_raw, eattr, E);
    }
}

// ---------------- K_pull: grid-stride warps, register BN accumulation --------
// Each warp processes ~N/nwarps nodes, accumulating BN sum/sq in REGISTERS.
// Flush once: plain STS to a per-warp smem slice, one sync, 128 threads
// reduce 8 slices -> 2 global atomics each. ZERO shared-memory atomics.
#define PULL_BLOCKS 592   // 4 per SM

__global__ __launch_bounds__(256)
void k_pull(const float* __restrict__ We, const float* __restrict__ be, int N)
{
    __shared__ float s_sum[8 * 128];
    __shared__ float s_sq [8 * 128];

    const int tid = threadIdx.x;
    const int warp = tid >> 5, lane = tid & 31;
    const int c0 = lane * 4;
    const int gw = blockIdx.x * 8 + warp;
    const int stride = PULL_BLOCKS * 8;

    float bsum[4] = {0.f, 0.f, 0.f, 0.f};
    float bsq [4] = {0.f, 0.f, 0.f, 0.f};

    for (int n = gw; n < N; n += stride) {
        const int j0 = g_off[n], j1 = g_off[n + 1];

        float4 acc = make_float4(0.f, 0.f, 0.f, 0.f);

        for (int base = j0; base < j1; base += 32) {
            int myidx = g_csr_src[base + lane];   // coalesced; overread bounded by MAXE
            int cnt = j1 - base; if (cnt > 32) cnt = 32;
            int t = 0;
            for (; t + 3 < cnt; t += 4) {
                int s0 = __shfl_sync(0xffffffffu, myidx, t);
                int s1 = __shfl_sync(0xffffffffu, myidx, t + 1);
                int s2 = __shfl_sync(0xffffffffu, myidx, t + 2);
                int s3 = __shfl_sync(0xffffffffu, myidx, t + 3);
                uint2 r0 = *(const uint2*)&g_x[(size_t)s0 * DOUT + c0];
                uint2 r1 = *(const uint2*)&g_x[(size_t)s1 * DOUT + c0];
                uint2 r2 = *(const uint2*)&g_x[(size_t)s2 * DOUT + c0];
                uint2 r3 = *(const uint2*)&g_x[(size_t)s3 * DOUT + c0];
                float2 a0 = __half22float2(*(__half2*)&r0.x);
                float2 b0 = __half22float2(*(__half2*)&r0.y);
                float2 a1 = __half22float2(*(__half2*)&r1.x);
                float2 b1 = __half22float2(*(__half2*)&r1.y);
                float2 a2 = __half22float2(*(__half2*)&r2.x);
                float2 b2 = __half22float2(*(__half2*)&r2.y);
                float2 a3 = __half22float2(*(__half2*)&r3.x);
                float2 b3 = __half22float2(*(__half2*)&r3.y);
                acc.x += (a0.x + a1.x) + (a2.x + a3.x);
                acc.y += (a0.y + a1.y) + (a2.y + a3.y);
                acc.z += (b0.x + b1.x) + (b2.x + b3.x);
                acc.w += (b0.y + b1.y) + (b2.y + b3.y);
            }
            for (; t < cnt; t++) {
                int s0 = __shfl_sync(0xffffffffu, myidx, t);
                uint2 r0 = *(const uint2*)&g_x[(size_t)s0 * DOUT + c0];
                float2 a0 = __half22float2(*(__half2*)&r0.x);
                float2 b0 = __half22float2(*(__half2*)&r0.y);
                acc.x += a0.x; acc.y += a0.y; acc.z += b0.x; acc.w += b0.y;
            }
        }

        float ea = 0.f;
        if (lane < EDIM) {
            ea = g_ea[(size_t)n * EDIM + lane];
            g_ea[(size_t)n * EDIM + lane] = 0.f;   // restore zero-invariant
        }
        float eav[EDIM];
        #pragma unroll
        for (int q = 0; q < EDIM; q++) eav[q] = __shfl_sync(0xffffffffu, ea, q);

        const float deg = (float)(j1 - j0);
        float4 b = *(const float4*)&be[c0];
        float4 elin = make_float4(b.x * deg, b.y * deg, b.z * deg, b.w * deg);

        const float4* W4 = (const float4*)We;
        #pragma unroll
        for (int q4 = 0; q4 < 4; q4++) {
            float4 w0 = W4[(c0 + 0) * 4 + q4];
            float4 w1 = W4[(c0 + 1) * 4 + q4];
            float4 w2 = W4[(c0 + 2) * 4 + q4];
            float4 w3 = W4[(c0 + 3) * 4 + q4];
            float e0v = eav[q4 * 4 + 0], e1v = eav[q4 * 4 + 1];
            float e2v = eav[q4 * 4 + 2], e3v = eav[q4 * 4 + 3];
            elin.x += w0.x * e0v + w0.y * e1v + w0.z * e2v + w0.w * e3v;
            elin.y += w1.x * e0v + w1.y * e1v + w1.z * e2v + w1.w * e3v;
            elin.z += w2.x * e0v + w2.y * e1v + w2.z * e2v + w2.w * e3v;
            elin.w += w3.x * e0v + w3.y * e1v + w3.z * e2v + w3.w * e3v;
        }

        float4 res = *(const float4*)&g_res[(size_t)n * DOUT + c0];
        float4 h;
        h.x = fmaxf(acc.x + elin.x, 0.f) + res.x;
        h.y = fmaxf(acc.y + elin.y, 0.f) + res.y;
        h.z = fmaxf(acc.z + elin.z, 0.f) + res.z;
        h.w = fmaxf(acc.w + elin.w, 0.f) + res.w;
        *(float4*)&g_h[(size_t)n * DOUT + c0] = h;

        bsum[0] += h.x; bsum[1] += h.y; bsum[2] += h.z; bsum[3] += h.w;
        bsq [0] += h.x * h.x; bsq[1] += h.y * h.y;
        bsq [2] += h.z * h.z; bsq[3] += h.w * h.w;
    }

    // flush: plain vector stores to per-warp slice (no atomics)
    *(float4*)&s_sum[warp * 128 + c0] = make_float4(bsum[0], bsum[1], bsum[2], bsum[3]);
    *(float4*)&s_sq [warp * 128 + c0] = make_float4(bsq[0],  bsq[1],  bsq[2],  bsq[3]);
    __syncthreads();

    if (tid < 128) {
        float t1 = 0.f, t2 = 0.f;
        #pragma unroll
        for (int w = 0; w < 8; w++) {
            t1 += s_sum[w * 128 + tid];
            t2 += s_sq [w * 128 + tid];
        }
        atomicAdd(&g_sum[tid],   t1);
        atomicAdd(&g_sumsq[tid], t2);
    }
}

// ---------------- K4: finalize BN stats (consumes + resets accumulators) -----
__global__ void k4_stats(const float* __restrict__ gamma,
                         const float* __restrict__ beta, int N)
{
    int c = threadIdx.x;
    float invN = 1.f / (float)N;
    float s  = g_sum[c];
    float s2 = g_sumsq[c];
    g_sum[c] = 0.f;
    g_sumsq[c] = 0.f;
    float mean = s * invN;
    float var  = s2 * invN - mean * mean;
    float rstd = rsqrtf(var + BN_EPS);
    float sc   = gamma[c] * rstd;
    g_scale[c] = sc;
    g_shift[c] = beta[c] - mean * sc;
}

// ---------------- K5: normalize ----------------------------------------------
__global__ __launch_bounds__(256)
void k5_norm(float* __restrict__ out, int total4)
{
    int idx = blockIdx.x * blockDim.x + threadIdx.x;
    if (idx >= total4) return;
    int c4 = (idx & (DOUT / 4 - 1)) * 4;
    float4 h  = *(const float4*)&g_h[idx * 4];
    float4 sc = *(const float4*)&g_scale[c4];
    float4 sh = *(const float4*)&g_shift[c4];
    float4 o;
    o.x = h.x * sc.x + sh.x;
    o.y = h.y * sc.y + sh.y;
    o.z = h.z * sc.z + sh.z;
    o.w = h.w * sc.w + sh.w;
    ((float4*)out)[idx] = o;
}

// ---------------- launch ------------------------------------------------------
extern "C" void kernel_launch(void* const* d_in, const int* in_sizes, int n_in,
                              void* d_out, int out_size)
{
    const float* feats = (const float*)d_in[0];
    const void*  ei    = d_in[1];
    const float* eattr = (const float*)d_in[2];
    const float* Wrel  = (const float*)d_in[3];
    const float* brel  = (const float*)d_in[4];
    const float* We    = (const float*)d_in[5];
    const float* be    = (const float*)d_in[6];
    const float* Wres  = (const float*)d_in[7];
    const float* bres  = (const float*)d_in[8];
    const float* gamma = (const float*)d_in[9];
    const float* beta  = (const float*)d_in[10];

    const int N = in_sizes[0] / DIN;
    const int E = in_sizes[2] / EDIM;

    static int smem_set = 0;
    if (!smem_set) {
        cudaFuncSetAttribute(k_fused,
                             cudaFuncAttributeMaxDynamicSharedMemorySize, K1_SMEM);
        smem_set = 1;
    }

    const int k1_blocks = ((N + 127) / 128) * 4;
    const int pl_blocks = (E + 255) / 256;

    // order: k_pull is launch #4 (the ncu-profiled launch)
    k_hist<<<(E + 255) / 256, 256>>>(ei, E);
    k_scanall<<<1, 1024>>>(N);
    k_fused<<<k1_blocks + pl_blocks, 256, K1_SMEM>>>(
        ei, eattr, E, feats, Wrel, brel, Wres, bres, N, k1_blocks);
    k_pull<<<PULL_BLOCKS, 256>>>(We, be, N);
    k4_stats<<<1, 128>>>(gamma, beta, N);
    int total4 = N * DOUT / 4;
    k5_norm<<<(total4 + 255) / 256, 256>>>((float*)d_out, total4);
}

// round 17
// speedup vs baseline: 1.3238x; 1.1981x over previous
#include <cuda_runtime.h>
#include <cuda_fp16.h>
#include <cstdint>

#define DIN  128
#define DOUT 128
#define EDIM 16
#define MAXN 50176
#define MAXE 819200
#define BN_EPS 1e-5f

// ---------------- device scratch (static; zero-initialized at load) ---------
// Invariant: g_cnt, g_sum, g_sumsq, g_ea are ZERO at the start of every run
// (statics zero-init; each run re-zeroes after use).
__device__ __half g_x [MAXN * DOUT];   // feats @ W_rel^T + b_rel  (fp16)
__device__ float g_res[MAXN * DOUT];   // relu(feats @ W_res^T + b_res)
__device__ float g_h  [MAXN * DOUT];   // pre-BN activations
__device__ float g_ea [MAXN * EDIM];   // scatter-add of edge_attr per dst
__device__ int   g_cnt[MAXN];          // per-dst degree (histogram)
__device__ int   g_off[MAXN + 1];      // CSR offsets
__device__ int   g_cur[MAXN];          // placement cursors
__device__ int   g_csr_src[MAXE];      // src node per CSR slot
__device__ float g_sum  [DOUT];
__device__ float g_sumsq[DOUT];
__device__ float g_scale[DOUT];
__device__ float g_shift[DOUT];
__device__ int   g_is64;               // edge_index dtype flag

__device__ __forceinline__ void red_add_v4(float* p, float4 v) {
    asm volatile("red.global.add.v4.f32 [%0], {%1,%2,%3,%4};"
                 :: "l"(p), "f"(v.x), "f"(v.y), "f"(v.z), "f"(v.w)
                 : "memory");
}

__device__ __forceinline__ uint32_t cvt_tf32(float a) {
    uint32_t r;
    asm("cvt.rna.tf32.f32 %0, %1;" : "=r"(r) : "f"(a));
    return r;
}

__device__ __forceinline__ void mma_tf32(float* d, const uint32_t* a, const uint32_t* b) {
    asm volatile(
        "mma.sync.aligned.m16n8k8.row.col.f32.tf32.tf32.f32 "
        "{%0,%1,%2,%3}, {%4,%5,%6,%7}, {%8,%9}, {%0,%1,%2,%3};"
        : "+f"(d[0]), "+f"(d[1]), "+f"(d[2]), "+f"(d[3])
        : "r"(a[0]), "r"(a[1]), "r"(a[2]), "r"(a[3]), "r"(b[0]), "r"(b[1]));
}

// ---------------- K_hist: per-block dtype detect + histogram over dst --------
__global__ __launch_bounds__(256)
void k_hist(const void* __restrict__ ei_raw, int E)
{
    __shared__ int blk_nz;
    const unsigned int* w = (const unsigned int*)ei_raw;
    if (threadIdx.x == 0) blk_nz = 0;
    __syncthreads();
    if (w[2 * threadIdx.x + 1] != 0u) atomicOr(&blk_nz, 1);
    __syncthreads();
    const int is64 = blk_nz ? 0 : 1;
    if (blockIdx.x == 0 && threadIdx.x == 0) g_is64 = is64;

    int e = blockIdx.x * blockDim.x + threadIdx.x;
    if (e >= E) return;
    int d = is64 ? (int)((const long long*)ei_raw)[E + e]
                 : ((const int*)ei_raw)[E + e];
    atomicAdd(&g_cnt[d], 1);
}

// ---------------- K_scanall: single-block coalesced exclusive scan -----------
__global__ __launch_bounds__(1024)
void k_scanall(int N)
{
    __shared__ int wsum[32];
    __shared__ int s_carry;
    const int tid = threadIdx.x, wid = tid >> 5, lane = tid & 31;
    if (tid == 0) s_carry = 0;
    __syncthreads();

    const int rounds = (N + 1023) / 1024;
    for (int r = 0; r < rounds; r++) {
        int i = r * 1024 + tid;
        int v = (i < N) ? g_cnt[i] : 0;
        int x = v;
        #pragma unroll
        for (int o = 1; o < 32; o <<= 1) {
            int y = __shfl_up_sync(0xffffffffu, x, o);
            if (lane >= o) x += y;
        }
        if (lane == 31) wsum[wid] = x;
        __syncthreads();
        if (wid == 0) {
            int s = wsum[lane];
            #pragma unroll
            for (int o = 1; o < 32; o <<= 1) {
                int y = __shfl_up_sync(0xffffffffu, s, o);
                if (lane >= o) s += y;
            }
            wsum[lane] = s;
        }
        __syncthreads();
        int woff = (wid > 0) ? wsum[wid - 1] : 0;
        int excl = s_carry + woff + x - v;
        if (i < N) {
            g_off[i] = excl;
            g_cur[i] = excl;
            g_cnt[i] = 0;                    // restore zero-invariant
        }
        __syncthreads();
        if (tid == 0) s_carry += wsum[31];
        __syncthreads();
    }
    if (tid == 0) g_off[N] = s_carry;
}

// ---------------- K1 body (device): tf32 GEMM tile ---------------------------
#define K1_KT       64
#define K1_PITCH    68
#define K1_AS_FL    (128 * K1_PITCH)        // 8704 floats
#define K1_BF_FL    (8 * 8 * 32 * 4)        // 8192 floats
#define K1_SMEM     ((K1_AS_FL + K1_BF_FL) * 4)   // 67584 bytes

__device__ void k1_body(int bx, int yy,
                        const float* __restrict__ feats,
                        const float* __restrict__ Wrel, const float* __restrict__ brel,
                        const float* __restrict__ Wres, const float* __restrict__ bres,
                        int N, float* smem)
{
    float* As = smem;
    float* Bf = smem + K1_AS_FL;

    const int tid   = threadIdx.x;
    const int m0    = bx * 128;
    const int mat   = yy >> 1;
    const int nhalf = yy & 1;

    const float* Wsel = (mat == 0) ? Wrel : Wres;
    const float* bsel = (mat == 0) ? brel : bres;
    const int nbase = nhalf * 64;

    const int warp = tid >> 5, lane = tid & 31;
    const int g = lane >> 2, tig = lane & 3;
    const int mwarp = warp >> 1;
    const int nwarp = warp & 1;
    const int am0 = mwarp * 32;

    float d[2][4][4];
    #pragma unroll
    for (int mi = 0; mi < 2; mi++)
        #pragma unroll
        for (int ns = 0; ns < 4; ns++)
            #pragma unroll
            for (int q = 0; q < 4; q++) d[mi][ns][q] = 0.f;

    for (int kt = 0; kt < DIN / K1_KT; kt++) {
        const int koff = kt * K1_KT;
        __syncthreads();
        for (int idx = tid; idx < 128 * 16; idx += 256) {
            int row = idx >> 4, c4 = idx & 15;
            int node = m0 + row;
            float4 v = (node < N)
                ? *(const float4*)&feats[(size_t)node * DIN + koff + c4 * 4]
                : make_float4(0.f, 0.f, 0.f, 0.f);
            *(float4*)&As[row * K1_PITCH + c4 * 4] = v;
        }
        for (int idx = tid; idx < 8 * 8 * 32; idx += 256) {
            int ks = idx >> 8;
            int ns = (idx >> 5) & 7;
            int ln = idx & 31;
            int gg = ln >> 2, tg = ln & 3;
            int nrow = nbase + ns * 8 + gg;
            const float* wr = &Wsel[(size_t)nrow * DIN + koff + ks * 8 + tg];
            float w0 = wr[0], w1 = wr[4];
            uint32_t h0 = cvt_tf32(w0);
            uint32_t h1 = cvt_tf32(w1);
            uint32_t l0 = cvt_tf32(w0 - __uint_as_float(h0));
            uint32_t l1 = cvt_tf32(w1 - __uint_as_float(h1));
            *(float4*)&Bf[(size_t)idx * 4] =
                make_float4(__uint_as_float(h0), __uint_as_float(h1),
                            __uint_as_float(l0), __uint_as_float(l1));
        }
        __syncthreads();

        #pragma unroll
        for (int ks = 0; ks < K1_KT / 8; ks++) {
            const int k0 = ks * 8;
            float af[8];
            #pragma unroll
            for (int mi = 0; mi < 2; mi++) {
                int r0 = am0 + mi * 16 + g;
                af[mi*4+0] = As[r0 * K1_PITCH + k0 + tig];
                af[mi*4+1] = As[(r0 + 8) * K1_PITCH + k0 + tig];
                af[mi*4+2] = As[r0 * K1_PITCH + k0 + tig + 4];
                af[mi*4+3] = As[(r0 + 8) * K1_PITCH + k0 + tig + 4];
            }
            uint32_t ah[8], al[8];
            #pragma unroll
            for (int q = 0; q < 8; q++) {
                ah[q] = cvt_tf32(af[q]);
                al[q] = cvt_tf32(af[q] - __uint_as_float(ah[q]));
            }
            #pragma unroll
            for (int nsl = 0; nsl < 4; nsl++) {
                const int nsg = nwarp * 4 + nsl;
                float4 b = *(const float4*)&Bf[((ks * 8 + nsg) * 32 + lane) * 4];
                uint32_t bh[2] = {__float_as_uint(b.x), __float_as_uint(b.y)};
                uint32_t bl[2] = {__float_as_uint(b.z), __float_as_uint(b.w)};
                #pragma unroll
                for (int mi = 0; mi < 2; mi++) {
                    mma_tf32(d[mi][nsl], ah + 4*mi, bh);
                    mma_tf32(d[mi][nsl], al + 4*mi, bh);
                    mma_tf32(d[mi][nsl], ah + 4*mi, bl);
                }
            }
        }
    }

    #pragma unroll
    for (int mi = 0; mi < 2; mi++) {
        const int rA = m0 + am0 + mi * 16 + g;
        #pragma unroll
        for (int nsl = 0; nsl < 4; nsl++) {
            const int col = nbase + (nwarp * 4 + nsl) * 8 + tig * 2;
            float b0 = bsel[col], b1 = bsel[col + 1];
            float v0 = d[mi][nsl][0] + b0, v1 = d[mi][nsl][1] + b1;
            float v2 = d[mi][nsl][2] + b0, v3 = d[mi][nsl][3] + b1;
            if (mat == 0) {
                if (rA < N)
                    *(__half2*)&g_x[(size_t)rA * DOUT + col] = __floats2half2_rn(v0, v1);
                if (rA + 8 < N)
                    *(__half2*)&g_x[(size_t)(rA + 8) * DOUT + col] = __floats2half2_rn(v2, v3);
            } else {
                v0 = fmaxf(v0, 0.f); v1 = fmaxf(v1, 0.f);
                v2 = fmaxf(v2, 0.f); v3 = fmaxf(v3, 0.f);
                if (rA < N)
                    *(float2*)&g_res[(size_t)rA * DOUT + col] = make_float2(v0, v1);
                if (rA + 8 < N)
                    *(float2*)&g_res[(size_t)(rA + 8) * DOUT + col] = make_float2(v2, v3);
            }
        }
    }
}

// ---------------- place body (device) ----------------------------------------
__device__ void place_body(int blk, const void* __restrict__ ei_raw,
                           const float* __restrict__ eattr, int E)
{
    int e = blk * 256 + threadIdx.x;
    if (e >= E) return;
    int s, d;
    if (g_is64) {
        const long long* p = (const long long*)ei_raw;
        s = (int)p[e]; d = (int)p[E + e];
    } else {
        const int* p = (const int*)ei_raw;
        s = p[e]; d = p[E + e];
    }
    int pos = atomicAdd(&g_cur[d], 1);
    g_csr_src[pos] = s;

    const float4* a4 = (const float4*)&eattr[(size_t)e * EDIM];
    float* dst = &g_ea[(size_t)d * EDIM];
    red_add_v4(dst + 0,  a4[0]);
    red_add_v4(dst + 4,  a4[1]);
    red_add_v4(dst + 8,  a4[2]);
    red_add_v4(dst + 12, a4[3]);
}

// ---------------- K_fused: k1 GEMM blocks + place blocks in one launch -------
__global__ __launch_bounds__(256)
void k_fused(const void* __restrict__ ei_raw, const float* __restrict__ eattr, int E,
             const float* __restrict__ feats,
             const float* __restrict__ Wrel, const float* __restrict__ brel,
             const float* __restrict__ Wres, const float* __restrict__ bres,
             int N, int k1_blocks)
{
    extern __shared__ float smem[];
    int bid = blockIdx.x;
    if (bid < k1_blocks) {
        k1_body(bid >> 2, bid & 3, feats, Wrel, brel, Wres, bres, N, smem);
    } else {
        place_body(bid - k1_blocks, ei_raw, eattr, E);
    }
}

// ---------------- K_pull: smem-transposed W + register BN accumulation -------
// We loaded ONCE per block into smem TRANSPOSED: Wt[q][c]. Per-node edge-linear
// reads Wt[q][c0..c0+3] as LDS.128 with lane-stride 16B -> warp-contiguous
// 512B -> conflict-free (4 cyc), vs 32-wavefront global loads before.
#define PULL_BLOCKS 592   // 4 per SM

__global__ __launch_bounds__(256)
void k_pull(const float* __restrict__ We, const float* __restrict__ be, int N)
{
    __shared__ float s_Wt[EDIM * 128];    // Wt[q][c] = We[c][q]
    __shared__ float s_sum[8 * 128];
    __shared__ float s_sq [8 * 128];

    const int tid = threadIdx.x;
    const int warp = tid >> 5, lane = tid & 31;
    const int c0 = lane * 4;
    const int gw = blockIdx.x * 8 + warp;
    const int stride = PULL_BLOCKS * 8;

    // transpose-load We (128x16) -> s_Wt (16x128); coalesced reads of We rows
    for (int idx = tid; idx < 128 * EDIM; idx += 256) {
        int c = idx >> 4, q = idx & 15;     // read We[c][q] coalesced-ish (64B runs)
        s_Wt[q * 128 + c] = We[idx];
    }
    __syncthreads();

    float bsum[4] = {0.f, 0.f, 0.f, 0.f};
    float bsq [4] = {0.f, 0.f, 0.f, 0.f};

    for (int n = gw; n < N; n += stride) {
        const int j0 = g_off[n], j1 = g_off[n + 1];

        float4 acc = make_float4(0.f, 0.f, 0.f, 0.f);

        for (int base = j0; base < j1; base += 32) {
            int myidx = g_csr_src[base + lane];   // coalesced; overread bounded by MAXE
            int cnt = j1 - base; if (cnt > 32) cnt = 32;
            int t = 0;
            for (; t + 3 < cnt; t += 4) {
                int s0 = __shfl_sync(0xffffffffu, myidx, t);
                int s1 = __shfl_sync(0xffffffffu, myidx, t + 1);
                int s2 = __shfl_sync(0xffffffffu, myidx, t + 2);
                int s3 = __shfl_sync(0xffffffffu, myidx, t + 3);
                uint2 r0 = *(const uint2*)&g_x[(size_t)s0 * DOUT + c0];
                uint2 r1 = *(const uint2*)&g_x[(size_t)s1 * DOUT + c0];
                uint2 r2 = *(const uint2*)&g_x[(size_t)s2 * DOUT + c0];
                uint2 r3 = *(const uint2*)&g_x[(size_t)s3 * DOUT + c0];
                float2 a0 = __half22float2(*(__half2*)&r0.x);
                float2 b0 = __half22float2(*(__half2*)&r0.y);
                float2 a1 = __half22float2(*(__half2*)&r1.x);
                float2 b1 = __half22float2(*(__half2*)&r1.y);
                float2 a2 = __half22float2(*(__half2*)&r2.x);
                float2 b2 = __half22float2(*(__half2*)&r2.y);
                float2 a3 = __half22float2(*(__half2*)&r3.x);
                float2 b3 = __half22float2(*(__half2*)&r3.y);
                acc.x += (a0.x + a1.x) + (a2.x + a3.x);
                acc.y += (a0.y + a1.y) + (a2.y + a3.y);
                acc.z += (b0.x + b1.x) + (b2.x + b3.x);
                acc.w += (b0.y + b1.y) + (b2.y + b3.y);
            }
            for (; t < cnt; t++) {
                int s0 = __shfl_sync(0xffffffffu, myidx, t);
                uint2 r0 = *(const uint2*)&g_x[(size_t)s0 * DOUT + c0];
                float2 a0 = __half22float2(*(__half2*)&r0.x);
                float2 b0 = __half22float2(*(__half2*)&r0.y);
                acc.x += a0.x; acc.y += a0.y; acc.z += b0.x; acc.w += b0.y;
            }
        }

        float ea = 0.f;
        if (lane < EDIM) {
            ea = g_ea[(size_t)n * EDIM + lane];
            g_ea[(size_t)n * EDIM + lane] = 0.f;   // restore zero-invariant
        }
        float eav[EDIM];
        #pragma unroll
        for (int q = 0; q < EDIM; q++) eav[q] = __shfl_sync(0xffffffffu, ea, q);

        const float deg = (float)(j1 - j0);
        float4 b = *(const float4*)&be[c0];
        float4 elin = make_float4(b.x * deg, b.y * deg, b.z * deg, b.w * deg);

        #pragma unroll
        for (int q = 0; q < EDIM; q++) {
            float4 w = *(const float4*)&s_Wt[q * 128 + c0];   // conflict-free LDS.128
            elin.x += w.x * eav[q];
            elin.y += w.y * eav[q];
            elin.z += w.z * eav[q];
            elin.w += w.w * eav[q];
        }

        float4 res = *(const float4*)&g_res[(size_t)n * DOUT + c0];
        float4 h;
        h.x = fmaxf(acc.x + elin.x, 0.f) + res.x;
        h.y = fmaxf(acc.y + elin.y, 0.f) + res.y;
        h.z = fmaxf(acc.z + elin.z, 0.f) + res.z;
        h.w = fmaxf(acc.w + elin.w, 0.f) + res.w;
        *(float4*)&g_h[(size_t)n * DOUT + c0] = h;

        bsum[0] += h.x; bsum[1] += h.y; bsum[2] += h.z; bsum[3] += h.w;
        bsq [0] += h.x * h.x; bsq[1] += h.y * h.y;
        bsq [2] += h.z * h.z; bsq[3] += h.w * h.w;
    }

    // flush: plain vector stores to per-warp slice (no atomics)
    *(float4*)&s_sum[warp * 128 + c0] = make_float4(bsum[0], bsum[1], bsum[2], bsum[3]);
    *(float4*)&s_sq [warp * 128 + c0] = make_float4(bsq[0],  bsq[1],  bsq[2],  bsq[3]);
    __syncthreads();

    if (tid < 128) {
        float t1 = 0.f, t2 = 0.f;
        #pragma unroll
        for (int w = 0; w < 8; w++) {
            t1 += s_sum[w * 128 + tid];
            t2 += s_sq [w * 128 + tid];
        }
        atomicAdd(&g_sum[tid],   t1);
        atomicAdd(&g_sumsq[tid], t2);
    }
}

// ---------------- K4: finalize BN stats (consumes + resets accumulators) -----
__global__ void k4_stats(const float* __restrict__ gamma,
                         const float* __restrict__ beta, int N)
{
    int c = threadIdx.x;
    float invN = 1.f / (float)N;
    float s  = g_sum[c];
    float s2 = g_sumsq[c];
    g_sum[c] = 0.f;
    g_sumsq[c] = 0.f;
    float mean = s * invN;
    float var  = s2 * invN - mean * mean;
    float rstd = rsqrtf(var + BN_EPS);
    float sc   = gamma[c] * rstd;
    g_scale[c] = sc;
    g_shift[c] = beta[c] - mean * sc;
}

// ---------------- K5: normalize ----------------------------------------------
__global__ __launch_bounds__(256)
void k5_norm(float* __restrict__ out, int total4)
{
    int idx = blockIdx.x * blockDim.x + threadIdx.x;
    if (idx >= total4) return;
    int c4 = (idx & (DOUT / 4 - 1)) * 4;
    float4 h  = *(const float4*)&g_h[idx * 4];
    float4 sc = *(const float4*)&g_scale[c4];
    float4 sh = *(const float4*)&g_shift[c4];
    float4 o;
    o.x = h.x * sc.x + sh.x;
    o.y = h.y * sc.y + sh.y;
    o.z = h.z * sc.z + sh.z;
    o.w = h.w * sc.w + sh.w;
    ((float4*)out)[idx] = o;
}

// ---------------- launch ------------------------------------------------------
extern "C" void kernel_launch(void* const* d_in, const int* in_sizes, int n_in,
                              void* d_out, int out_size)
{
    const float* feats = (const float*)d_in[0];
    const void*  ei    = d_in[1];
    const float* eattr = (const float*)d_in[2];
    const float* Wrel  = (const float*)d_in[3];
    const float* brel  = (const float*)d_in[4];
    const float* We    = (const float*)d_in[5];
    const float* be    = (const float*)d_in[6];
    const float* Wres  = (const float*)d_in[7];
    const float* bres  = (const float*)d_in[8];
    const float* gamma = (const float*)d_in[9];
    const float* beta  = (const float*)d_in[10];

    const int N = in_sizes[0] / DIN;
    const int E = in_sizes[2] / EDIM;

    static int smem_set = 0;
    if (!smem_set) {
        cudaFuncSetAttribute(k_fused,
                             cudaFuncAttributeMaxDynamicSharedMemorySize, K1_SMEM);
        smem_set = 1;
    }

    const int k1_blocks = ((N + 127) / 128) * 4;
    const int pl_blocks = (E + 255) / 256;

    // order: k_pull is launch #4 (the ncu-profiled launch)
    k_hist<<<(E + 255) / 256, 256>>>(ei, E);
    k_scanall<<<1, 1024>>>(N);
    k_fused<<<k1_blocks + pl_blocks, 256, K1_SMEM>>>(
        ei, eattr, E, feats, Wrel, brel, Wres, bres, N, k1_blocks);
    k_pull<<<PULL_BLOCKS, 256>>>(We, be, N);
    k4_stats<<<1, 128>>>(gamma, beta, N);
    int total4 = N * DOUT / 4;
    k5_norm<<<(total4 + 255) / 256, 256>>>((float*)d_out, total4);
}